// round 12
// baseline (speedup 1.0000x reference)
#include <cuda_runtime.h>
#include <cstdint>

#define BATCH 4096
#define IN_F 128
#define OUT_F 128
#define NW (IN_F * OUT_F)
#define NCHUNK 37            // 36 x-chunks (9e x 4 i-groups) + 1 bias chunk
#define XP 164               // x smem pitch (floats) = 41 float4

// B operand in EXACT mma-fragment order (tf32-rounded):
// d_Btf[((c*16 + nb)*2 + p)*128 + lane*4 + e2]
//   = Bt[nb*8 + (lane>>2)][c*32 + 16p + 8*(e2>>1) + 4*(e2&1) + (lane&3)]
__device__ float d_Btf[NCHUNK * 16 * 2 * 128];

// ---------------------------------------------------------------------------
// Helpers (baseline PTX only — toolchain compiles via compute_103, no tcgen05)
// ---------------------------------------------------------------------------
__device__ __forceinline__ float tf32r(float x) {
    uint32_t r;
    asm("cvt.rn.tf32.f32 %0, %1;" : "=r"(r) : "f"(x));
    return __uint_as_float(r);
}
__device__ __forceinline__ uint32_t tf32u(float x) {
    uint32_t r;
    asm("cvt.rn.tf32.f32 %0, %1;" : "=r"(r) : "f"(x));
    return r;
}
__device__ __forceinline__ void mma_tf32(float& d0, float& d1, float& d2, float& d3,
                                         uint32_t a0, uint32_t a1, uint32_t a2, uint32_t a3,
                                         uint32_t b0, uint32_t b1) {
    asm volatile(
        "mma.sync.aligned.m16n8k8.row.col.f32.tf32.tf32.f32 "
        "{%0,%1,%2,%3}, {%4,%5,%6,%7}, {%8,%9}, {%0,%1,%2,%3};"
        : "+f"(d0), "+f"(d1), "+f"(d2), "+f"(d3)
        : "r"(a0), "r"(a1), "r"(a2), "r"(a3), "r"(b0), "r"(b1));
}

// ---------------------------------------------------------------------------
// Prep: build d_Btf. Block = (c, nb); thread -> (p, lane, e2). Coalesced write.
// ---------------------------------------------------------------------------
__global__ __launch_bounds__(256) void b_kernel(const float* __restrict__ gen_W,
                                                const float* __restrict__ gen_b) {
    const int c  = blockIdx.x >> 4;
    const int nb = blockIdx.x & 15;
    const int tid = threadIdx.x;
    const int p  = tid >> 7;
    const int l  = (tid >> 2) & 31;
    const int e2 = tid & 3;
    const int g = l >> 2, q = l & 3;
    const int o = nb * 8 + g;
    const int k = c * 32 + 16 * p + 8 * (e2 >> 1) + 4 * (e2 & 1) + q;
    float v;
    if (k < 1152) {
        const int e = k >> 7, i = k & 127, p8 = o * 128 + i;
        v = (e < 8) ? gen_W[p8 * 8 + e] : gen_b[p8];
    } else if (k < 1161) {
        const int e = k - 1152;
        v = (e < 8) ? gen_W[(NW + o) * 8 + e] : gen_b[NW + o];
    } else v = 0.f;
    d_Btf[blockIdx.x * 256 + tid] = tf32r(v);
}

// ---------------------------------------------------------------------------
// Fused GEMM: out = U @ Bt^T with U[b,k]=c[b,e]*x[b,i] never materialized.
// CTA: 512 thr (16 warps), tile M=64 x N=64; grid 128 = (m-tile) x (n-half).
// Warp tile M16 x N16: wr=wid&3 (16 rows), wc=wid>>2 (16 cols). Full K per
// warp, no mainloop barriers. ii-outer A preload (16 regs live), fold per
// chunk: acc += c_e * (x_ii . B_c). ~90 regs -> 16 warps = full RF.
// ---------------------------------------------------------------------------
__global__ __launch_bounds__(512, 1) void gemm_kernel(
    const float* __restrict__ x,
    const float* __restrict__ features,
    const float* __restrict__ fc0_W, const float* __restrict__ fc0_b,
    const float* __restrict__ a0p,
    const float* __restrict__ fc1_W, const float* __restrict__ fc1_b,
    const float* __restrict__ a1p,
    float* __restrict__ out)
{
    __shared__ __align__(16) float xs[64 * XP];   // 42 KB: cols 0-127 x, 128-136 c, ..163 zero

    const int tid = threadIdx.x, wid = tid >> 5, lid = tid & 31;
    const int mt = blockIdx.x >> 1, nh = blockIdx.x & 1;
    const int b0row = mt * 64;
    const int wr = wid & 3, wc = wid >> 2;        // wc 0..3
    const int m0 = wr * 16;
    const int nbb = nh * 8 + wc * 2;              // n-block base (units of 8 cols), ni in {0,1}
    const int g = lid >> 2, q = lid & 3;

    // ---- x tile: 64 rows x 128 cols (2048 float4, 4/thread, coalesced) ----
    {
        const float4* xg = (const float4*)(x + (size_t)b0row * IN_F);
        float4* xs4 = (float4*)xs;
        #pragma unroll
        for (int j = 0; j < 4; j++) {
            const int idx = tid + 512 * j;
            const int r = idx >> 5, c4 = idx & 31;
            xs4[r * 41 + c4] = xg[idx];
        }
    }

    // ---- tiny MLP: threads 0-63, one sample each; coeffs -> cols 128-136 ----
    if (tid < 64) {
        const int b = b0row + tid;
        const float a0 = a0p[0], a1 = a1p[0];
        float h0[16];
        #pragma unroll
        for (int j = 0; j < 16; j++) {
            float s = fc0_b[j];
            #pragma unroll
            for (int k = 0; k < 10; k++)
                s += features[b * 10 + k] * fc0_W[j * 10 + k];
            h0[j] = (s >= 0.f) ? s : a0 * s;
        }
        float* xr = xs + tid * XP + 128;
        #pragma unroll
        for (int e = 0; e < 8; e++) {
            float s = fc1_b[e];
            #pragma unroll
            for (int j = 0; j < 16; j++)
                s += h0[j] * fc1_W[e * 16 + j];
            xr[e] = (s >= 0.f) ? s : a1 * s;
        }
        xr[8] = 1.f;
        #pragma unroll
        for (int j = 9; j < 36; j++) xr[j] = 0.f;   // zero cols 137..163
    }

    // ---- B fragment loads: 4 x LDG.128 per chunk, register double-buffer ----
    const float4* bp = (const float4*)d_Btf;      // f4 index: ((c*16+nb)*2+p)*32 + lane
    float4 br[2][4];                               // [buf][ni*2+p]
    #define LOADB(buf, c)                                                     \
        _Pragma("unroll")                                                     \
        for (int ni = 0; ni < 2; ni++) {                                      \
            _Pragma("unroll")                                                 \
            for (int p = 0; p < 2; p++)                                       \
                br[buf][ni * 2 + p] =                                         \
                    __ldg(bp + (((c) * 16 + nbb + ni) * 2 + p) * 32 + lid);   \
        }
    LOADB(0, 0)                                   // first chunk (t=0 -> c=0)

    __syncthreads();

    const float* x0 = xs + (m0 + g) * XP;
    const float* x1 = x0 + 8 * XP;

    float acc[8];                                  // [ni*4+r]
    #pragma unroll
    for (int r = 0; r < 8; r++) acc[r] = 0.f;

    // ---- mainloop: ii outer (A preload 16 regs), e inner, fold per chunk ----
    // t = ii*9 + e ; chunk c(t) = (t%9)*4 + t/9 ; buf = t&1.
    #pragma unroll
    for (int ii = 0; ii < 4; ii++) {
        uint32_t ua0[4], ua1[4], ua2[4], ua3[4];
        #pragma unroll
        for (int ki = 0; ki < 4; ki++) {
            const int col = ii * 32 + ki * 8 + q;
            ua0[ki] = tf32u(x0[col]);
            ua1[ki] = tf32u(x1[col]);
            ua2[ki] = tf32u(x0[col + 4]);
            ua3[ki] = tf32u(x1[col + 4]);
        }

        #pragma unroll
        for (int e = 0; e < 9; e++) {
            const int t = ii * 9 + e;
            // prefetch next chunk in sequence (t+1); t=35 prefetches bias c=36
            if (t < 36) {
                const int tn = t + 1;
                const int cn = (tn < 36) ? ((tn % 9) * 4 + tn / 9) : 36;
                LOADB(tn & 1, cn)
            }

            float z[8];
            #pragma unroll
            for (int r = 0; r < 8; r++) z[r] = 0.f;

            #pragma unroll
            for (int ki = 0; ki < 4; ki++) {
                const uint32_t a0 = ua0[ki], a1 = ua1[ki];
                const uint32_t a2 = ua2[ki], a3 = ua3[ki];
                #pragma unroll
                for (int ni = 0; ni < 2; ni++) {
                    const float4 f = br[t & 1][ni * 2 + (ki >> 1)];
                    const uint32_t bb0 = (ki & 1) ? __float_as_uint(f.z) : __float_as_uint(f.x);
                    const uint32_t bb1 = (ki & 1) ? __float_as_uint(f.w) : __float_as_uint(f.y);
                    mma_tf32(z[ni * 4 + 0], z[ni * 4 + 1], z[ni * 4 + 2], z[ni * 4 + 3],
                             a0, a1, a2, a3, bb0, bb1);
                }
            }

            const float cb0 = x0[128 + e];
            const float cb1 = x1[128 + e];
            #pragma unroll
            for (int ni = 0; ni < 2; ni++) {
                acc[ni * 4 + 0] += cb0 * z[ni * 4 + 0];
                acc[ni * 4 + 1] += cb0 * z[ni * 4 + 1];
                acc[ni * 4 + 2] += cb1 * z[ni * 4 + 2];
                acc[ni * 4 + 3] += cb1 * z[ni * 4 + 3];
            }
        }
    }

    // ---- bias chunk c=36 (buf 0): A = coeff cols, scale 1 ----
    {
        #pragma unroll
        for (int ki = 0; ki < 4; ki++) {
            const int col = 128 + ki * 8 + q;
            const uint32_t a0 = tf32u(x0[col]);
            const uint32_t a1 = tf32u(x1[col]);
            const uint32_t a2 = tf32u(x0[col + 4]);
            const uint32_t a3 = tf32u(x1[col + 4]);
            #pragma unroll
            for (int ni = 0; ni < 2; ni++) {
                const float4 f = br[0][ni * 2 + (ki >> 1)];
                const uint32_t bb0 = (ki & 1) ? __float_as_uint(f.z) : __float_as_uint(f.x);
                const uint32_t bb1 = (ki & 1) ? __float_as_uint(f.w) : __float_as_uint(f.y);
                mma_tf32(acc[ni * 4 + 0], acc[ni * 4 + 1], acc[ni * 4 + 2], acc[ni * 4 + 3],
                         a0, a1, a2, a3, bb0, bb1);
            }
        }
    }

    // ---- stores: rows b0row+m0+g / +8, cols nh*64 + wc*16 + ni*8 + 2q ----
    const int colbase = nh * 64 + wc * 16;
    #pragma unroll
    for (int ni = 0; ni < 2; ni++) {
        const int col = colbase + ni * 8 + 2 * q;
        float2 lo = make_float2(acc[ni * 4 + 0], acc[ni * 4 + 1]);
        float2 hi = make_float2(acc[ni * 4 + 2], acc[ni * 4 + 3]);
        *(float2*)(out + (size_t)(b0row + m0 + g)     * OUT_F + col) = lo;
        *(float2*)(out + (size_t)(b0row + m0 + g + 8) * OUT_F + col) = hi;
    }
}

// ---------------------------------------------------------------------------
extern "C" void kernel_launch(void* const* d_in, const int* in_sizes, int n_in,
                              void* d_out, int out_size) {
    const float* x        = (const float*)d_in[0];
    const float* features = (const float*)d_in[1];
    const float* fc0_W    = (const float*)d_in[2];
    const float* fc0_b    = (const float*)d_in[3];
    const float* a0       = (const float*)d_in[4];
    const float* fc1_W    = (const float*)d_in[5];
    const float* fc1_b    = (const float*)d_in[6];
    const float* a1       = (const float*)d_in[7];
    const float* gen_W    = (const float*)d_in[8];
    const float* gen_b    = (const float*)d_in[9];
    float* out = (float*)d_out;

    b_kernel<<<NCHUNK * 16, 256>>>(gen_W, gen_b);
    gemm_kernel<<<128, 512>>>(x, features, fc0_W, fc0_b, a0,
                              fc1_W, fc1_b, a1, out);
}

// round 13
// speedup vs baseline: 1.3284x; 1.3284x over previous
#include <cuda_runtime.h>
#include <cstdint>

#define BATCH 4096
#define IN_F 128
#define OUT_F 128
#define NW (IN_F * OUT_F)
#define NCHUNK 37            // 36 x-chunks (9e x 4 i-groups) + 1 bias chunk
#define XP 164               // x smem pitch (floats) = 41 float4

// B operand in EXACT mma-fragment order (tf32-rounded):
// d_Btf[((c*16 + nb)*2 + p)*128 + lane*4 + e2]
__device__ float d_Btf[NCHUNK * 16 * 2 * 128];

// ---------------------------------------------------------------------------
// Helpers (baseline PTX only — toolchain compiles via compute_103, no tcgen05)
// ---------------------------------------------------------------------------
__device__ __forceinline__ float tf32r(float x) {
    uint32_t r;
    asm("cvt.rn.tf32.f32 %0, %1;" : "=r"(r) : "f"(x));
    return __uint_as_float(r);
}
__device__ __forceinline__ uint32_t tf32u(float x) {
    uint32_t r;
    asm("cvt.rn.tf32.f32 %0, %1;" : "=r"(r) : "f"(x));
    return r;
}
__device__ __forceinline__ void mma_tf32(float& d0, float& d1, float& d2, float& d3,
                                         uint32_t a0, uint32_t a1, uint32_t a2, uint32_t a3,
                                         uint32_t b0, uint32_t b1) {
    asm volatile(
        "mma.sync.aligned.m16n8k8.row.col.f32.tf32.tf32.f32 "
        "{%0,%1,%2,%3}, {%4,%5,%6,%7}, {%8,%9}, {%0,%1,%2,%3};"
        : "+f"(d0), "+f"(d1), "+f"(d2), "+f"(d3)
        : "r"(a0), "r"(a1), "r"(a2), "r"(a3), "r"(b0), "r"(b1));
}

// ---------------------------------------------------------------------------
// Prep: build d_Btf. Block = (c, nb); thread -> (p, lane, e2). Coalesced write.
// ---------------------------------------------------------------------------
__global__ __launch_bounds__(256) void b_kernel(const float* __restrict__ gen_W,
                                                const float* __restrict__ gen_b) {
    const int c  = blockIdx.x >> 4;
    const int nb = blockIdx.x & 15;
    const int tid = threadIdx.x;
    const int p  = tid >> 7;
    const int l  = (tid >> 2) & 31;
    const int e2 = tid & 3;
    const int g = l >> 2, q = l & 3;
    const int o = nb * 8 + g;
    const int k = c * 32 + 16 * p + 8 * (e2 >> 1) + 4 * (e2 & 1) + q;
    float v;
    if (k < 1152) {
        const int e = k >> 7, i = k & 127, p8 = o * 128 + i;
        v = (e < 8) ? gen_W[p8 * 8 + e] : gen_b[p8];
    } else if (k < 1161) {
        const int e = k - 1152;
        v = (e < 8) ? gen_W[(NW + o) * 8 + e] : gen_b[NW + o];
    } else v = 0.f;
    d_Btf[blockIdx.x * 256 + tid] = tf32r(v);
}

// ---------------------------------------------------------------------------
// Fused GEMM (R11 structure + deeper B pipeline):
// CTA: 256 thr (8 warps), tile M=64 x N=64; grid 128 = (m-tile) x (n-half).
// Warp tile M16 x N32: wr=wid&3, wc=wid>>2. Full K per warp, no mainloop
// barriers. x-tile pre-rounded to tf32 in smem -> A-frags are raw LDS
// bit-casts loaded per-ii (16 regs live). B: 3-buffer register ring, prefetch
// distance 2 (covers L2 latency). e-outer z-fold (amortized scale).
// ---------------------------------------------------------------------------
__global__ __launch_bounds__(256, 1) void gemm_kernel(
    const float* __restrict__ x,
    const float* __restrict__ features,
    const float* __restrict__ fc0_W, const float* __restrict__ fc0_b,
    const float* __restrict__ a0p,
    const float* __restrict__ fc1_W, const float* __restrict__ fc1_b,
    const float* __restrict__ a1p,
    float* __restrict__ out)
{
    __shared__ __align__(16) float xs[64 * XP];   // cols 0-127: tf32(x); 128-136: c (fp32)

    const int tid = threadIdx.x, wid = tid >> 5, lid = tid & 31;
    const int mt = blockIdx.x >> 1, nh = blockIdx.x & 1;
    const int b0row = mt * 64;
    const int wr = wid & 3, wc = wid >> 2;        // 4 m-warps x 2 n-warps
    const int m0 = wr * 16;
    const int nbb = nh * 8 + wc * 4;              // n-block base (units of 8 cols), ni 0..3
    const int g = lid >> 2, q = lid & 3;

    // ---- B fragment loads: 8 x LDG.128 per chunk, 3-buffer ring, dist 2 ----
    const float4* bp = (const float4*)d_Btf;      // f4 index: ((c*16+nb)*2+p)*32 + lane
    float4 br[3][8];                               // [buf][ni*2+p]
    #define LOADB(buf, c)                                                     \
        _Pragma("unroll")                                                     \
        for (int ni = 0; ni < 4; ni++) {                                      \
            _Pragma("unroll")                                                 \
            for (int p = 0; p < 2; p++)                                       \
                br[buf][ni * 2 + p] =                                         \
                    __ldg(bp + (((c) * 16 + nbb + ni) * 2 + p) * 32 + lid);   \
        }
    LOADB(0, 0)
    LOADB(1, 1)

    // ---- x tile: 64 rows x 128 cols, PRE-ROUNDED to tf32 at fill ----
    {
        const float4* xg = (const float4*)(x + (size_t)b0row * IN_F);
        float4* xs4 = (float4*)xs;
        #pragma unroll
        for (int j = 0; j < 8; j++) {
            const int idx = tid + 256 * j;
            const int r = idx >> 5, c4 = idx & 31;
            float4 v = xg[idx];
            v.x = tf32r(v.x); v.y = tf32r(v.y);
            v.z = tf32r(v.z); v.w = tf32r(v.w);
            xs4[r * 41 + c4] = v;
        }
    }

    // ---- tiny MLP: threads 0-63; coeffs (fp32) -> cols 128-136, rest 0 ----
    if (tid < 64) {
        const int b = b0row + tid;
        const float a0 = a0p[0], a1 = a1p[0];
        float h0[16];
        #pragma unroll
        for (int j = 0; j < 16; j++) {
            float s = fc0_b[j];
            #pragma unroll
            for (int k = 0; k < 10; k++)
                s += features[b * 10 + k] * fc0_W[j * 10 + k];
            h0[j] = (s >= 0.f) ? s : a0 * s;
        }
        float* xr = xs + tid * XP + 128;
        #pragma unroll
        for (int e = 0; e < 8; e++) {
            float s = fc1_b[e];
            #pragma unroll
            for (int j = 0; j < 16; j++)
                s += h0[j] * fc1_W[e * 16 + j];
            xr[e] = (s >= 0.f) ? s : a1 * s;
        }
        xr[8] = 1.f;
        #pragma unroll
        for (int j = 9; j < 36; j++) xr[j] = 0.f;
    }
    __syncthreads();

    const float* x0 = xs + (m0 + g) * XP;
    const float* x1 = x0 + 8 * XP;

    float acc[16];                                 // [ni*4+r]
    #pragma unroll
    for (int r = 0; r < 16; r++) acc[r] = 0.f;

    // ---- mainloop: e outer (z-fold), ii inner; prefetch c+2 into (c+2)%3 ----
    #pragma unroll
    for (int e = 0; e < 9; e++) {
        float z[16];
        #pragma unroll
        for (int r = 0; r < 16; r++) z[r] = 0.f;

        #pragma unroll
        for (int ii = 0; ii < 4; ii++) {
            const int c = e * 4 + ii;
            if (c + 2 <= 36) LOADB((c + 2) % 3, c + 2)

            // A-frags: raw bit-cast LDS from pre-rounded x tile
            uint32_t ua0[4], ua1[4], ua2[4], ua3[4];
            #pragma unroll
            for (int ki = 0; ki < 4; ki++) {
                const int col = ii * 32 + ki * 8 + q;
                ua0[ki] = __float_as_uint(x0[col]);
                ua1[ki] = __float_as_uint(x1[col]);
                ua2[ki] = __float_as_uint(x0[col + 4]);
                ua3[ki] = __float_as_uint(x1[col + 4]);
            }

            #pragma unroll
            for (int ki = 0; ki < 4; ki++) {
                #pragma unroll
                for (int ni = 0; ni < 4; ni++) {
                    const float4 f = br[c % 3][ni * 2 + (ki >> 1)];
                    const uint32_t bb0 = (ki & 1) ? __float_as_uint(f.z) : __float_as_uint(f.x);
                    const uint32_t bb1 = (ki & 1) ? __float_as_uint(f.w) : __float_as_uint(f.y);
                    mma_tf32(z[ni * 4 + 0], z[ni * 4 + 1], z[ni * 4 + 2], z[ni * 4 + 3],
                             ua0[ki], ua1[ki], ua2[ki], ua3[ki], bb0, bb1);
                }
            }
        }

        const float cb0 = x0[128 + e];
        const float cb1 = x1[128 + e];
        #pragma unroll
        for (int ni = 0; ni < 4; ni++) {
            acc[ni * 4 + 0] += cb0 * z[ni * 4 + 0];
            acc[ni * 4 + 1] += cb0 * z[ni * 4 + 1];
            acc[ni * 4 + 2] += cb1 * z[ni * 4 + 2];
            acc[ni * 4 + 3] += cb1 * z[ni * 4 + 3];
        }
    }

    // ---- bias chunk c=36 (buf 36%3 == 0): A = tf32(coeff cols), scale 1 ----
    {
        #pragma unroll
        for (int ki = 0; ki < 4; ki++) {
            const int col = 128 + ki * 8 + q;
            const uint32_t a0 = tf32u(x0[col]);
            const uint32_t a1 = tf32u(x1[col]);
            const uint32_t a2 = tf32u(x0[col + 4]);
            const uint32_t a3 = tf32u(x1[col + 4]);
            #pragma unroll
            for (int ni = 0; ni < 4; ni++) {
                const float4 f = br[0][ni * 2 + (ki >> 1)];
                const uint32_t bb0 = (ki & 1) ? __float_as_uint(f.z) : __float_as_uint(f.x);
                const uint32_t bb1 = (ki & 1) ? __float_as_uint(f.w) : __float_as_uint(f.y);
                mma_tf32(acc[ni * 4 + 0], acc[ni * 4 + 1], acc[ni * 4 + 2], acc[ni * 4 + 3],
                         a0, a1, a2, a3, bb0, bb1);
            }
        }
    }

    // ---- stores: rows b0row+m0+g / +8, cols nh*64 + wc*32 + ni*8 + 2q ----
    const int colbase = nh * 64 + wc * 32;
    #pragma unroll
    for (int ni = 0; ni < 4; ni++) {
        const int col = colbase + ni * 8 + 2 * q;
        float2 lo = make_float2(acc[ni * 4 + 0], acc[ni * 4 + 1]);
        float2 hi = make_float2(acc[ni * 4 + 2], acc[ni * 4 + 3]);
        *(float2*)(out + (size_t)(b0row + m0 + g)     * OUT_F + col) = lo;
        *(float2*)(out + (size_t)(b0row + m0 + g + 8) * OUT_F + col) = hi;
    }
}

// ---------------------------------------------------------------------------
extern "C" void kernel_launch(void* const* d_in, const int* in_sizes, int n_in,
                              void* d_out, int out_size) {
    const float* x        = (const float*)d_in[0];
    const float* features = (const float*)d_in[1];
    const float* fc0_W    = (const float*)d_in[2];
    const float* fc0_b    = (const float*)d_in[3];
    const float* a0       = (const float*)d_in[4];
    const float* fc1_W    = (const float*)d_in[5];
    const float* fc1_b    = (const float*)d_in[6];
    const float* a1       = (const float*)d_in[7];
    const float* gen_W    = (const float*)d_in[8];
    const float* gen_b    = (const float*)d_in[9];
    float* out = (float*)d_out;

    b_kernel<<<NCHUNK * 16, 256>>>(gen_W, gen_b);
    gemm_kernel<<<128, 256>>>(x, features, fc0_W, fc0_b, a0,
                              fc1_W, fc1_b, a1, out);
}